// round 8
// baseline (speedup 1.0000x reference)
#include <cuda_runtime.h>

#define NPTS 40000
#define KN 16
#define CH 128
#define CS 16          // C / S
#define CHP 132        // padded row stride for 128-wide rows
#define GRIDX 592      // 4 blocks/SM * 148 SMs, persistent
#define EPSBN 1e-5f

// ---------------- scratch (no allocation allowed -> __device__ globals) -------------
__device__ float g_q[NPTS * CH];
__device__ float g_k[NPTS * CH];
__device__ float g_v[NPTS * CH];
__device__ float g_W1T[CS * CH];   // folded (Ww1 * s1)^T
__device__ float g_sw[CH];
__device__ float g_shw[CH];
__device__ float g_b1f[CS];
__device__ float g_Wp1f[9];
__device__ float g_bp1f[3];

__device__ __forceinline__ void ffma2(unsigned long long& d,
                                      unsigned long long a,
                                      unsigned long long b) {
    asm("fma.rn.f32x2 %0, %1, %2, %0;" : "+l"(d) : "l"(a), "l"(b));
}
__device__ __forceinline__ unsigned long long dup2(float f) {
    unsigned int u = __float_as_uint(f);
    return ((unsigned long long)u << 32) | (unsigned long long)u;
}
__device__ __forceinline__ float lo32(unsigned long long v) {
    return __uint_as_float((unsigned int)v);
}
__device__ __forceinline__ float hi32(unsigned long long v) {
    return __uint_as_float((unsigned int)(v >> 32));
}

// ---------------- kernel 0: fold BN params -----------------------------------------
__global__ void prep_kernel(const float* __restrict__ w_gamma, const float* __restrict__ w_beta,
                            const float* __restrict__ w_mean, const float* __restrict__ w_var,
                            const float* __restrict__ Ww1, const float* __restrict__ bw1,
                            const float* __restrict__ w1_gamma, const float* __restrict__ w1_beta,
                            const float* __restrict__ w1_mean, const float* __restrict__ w1_var,
                            const float* __restrict__ Wp1, const float* __restrict__ bp1,
                            const float* __restrict__ p_gamma, const float* __restrict__ p_beta,
                            const float* __restrict__ p_mean, const float* __restrict__ p_var) {
    int t = threadIdx.x;
    if (t < CH) {
        float s = w_gamma[t] * rsqrtf(w_var[t] + EPSBN);
        g_sw[t] = s;
        g_shw[t] = w_beta[t] - w_mean[t] * s;
    }
    for (int idx = t; idx < CS * CH; idx += blockDim.x) {
        int j = idx / CH, c = idx % CH;
        float s1 = w1_gamma[j] * rsqrtf(w1_var[j] + EPSBN);
        g_W1T[idx] = Ww1[c * CS + j] * s1;
    }
    if (t < CS) {
        float s1 = w1_gamma[t] * rsqrtf(w1_var[t] + EPSBN);
        g_b1f[t] = (bw1[t] - w1_mean[t]) * s1 + w1_beta[t];
    }
    if (t < 9) {
        int o = t % 3;
        float sp = p_gamma[o] * rsqrtf(p_var[o] + EPSBN);
        g_Wp1f[t] = Wp1[t] * sp;
    }
    if (t < 3) {
        float sp = p_gamma[t] * rsqrtf(p_var[t] + EPSBN);
        g_bp1f[t] = (bp1[t] - p_mean[t]) * sp + p_beta[t];
    }
}

// ---------------- kernel 1: fused q/k/v GEMM (unchanged) ----------------------------
__global__ __launch_bounds__(256, 2) void qkv_gemm(
    const float* __restrict__ x,
    const float* __restrict__ Wq, const float* __restrict__ bq,
    const float* __restrict__ Wk, const float* __restrict__ bk,
    const float* __restrict__ Wv, const float* __restrict__ bv) {
    const float* W;
    const float* bias;
    float* out;
    if (blockIdx.y == 0)      { W = Wq; bias = bq; out = g_q; }
    else if (blockIdx.y == 1) { W = Wk; bias = bk; out = g_k; }
    else                      { W = Wv; bias = bv; out = g_v; }

    __shared__ __align__(16) unsigned long long A2s[16][64];
    __shared__ __align__(16) float Bs[16][128];

    const int tid = threadIdx.x;
    const int tm = tid >> 5;
    const int tn = tid & 31;
    const int row0 = blockIdx.x * 64;

    unsigned long long acc[8][2];
#pragma unroll
    for (int r = 0; r < 8; r++) { acc[r][0] = 0ULL; acc[r][1] = 0ULL; }

    for (int kt = 0; kt < 8; kt++) {
        const int k0 = kt * 16;
        {
            int ar = tid >> 2;
            int ac = (tid & 3) * 4;
            float4 av = *(const float4*)&x[(row0 + ar) * CH + k0 + ac];
            A2s[ac + 0][ar] = dup2(av.x);
            A2s[ac + 1][ar] = dup2(av.y);
            A2s[ac + 2][ar] = dup2(av.z);
            A2s[ac + 3][ar] = dup2(av.w);
        }
#pragma unroll
        for (int i = 0; i < 2; i++) {
            int f4 = tid * 2 + i;
            int bkr = f4 >> 5;
            int bc = (f4 & 31) * 4;
            *(float4*)&Bs[bkr][bc] = *(const float4*)&W[(k0 + bkr) * CH + bc];
        }
        __syncthreads();
#pragma unroll
        for (int kk = 0; kk < 16; kk++) {
            unsigned long long b0 = *(const unsigned long long*)&Bs[kk][tn * 4];
            unsigned long long b1 = *(const unsigned long long*)&Bs[kk][tn * 4 + 2];
#pragma unroll
            for (int r = 0; r < 8; r++) {
                unsigned long long a = A2s[kk][tm * 8 + r];
                ffma2(acc[r][0], a, b0);
                ffma2(acc[r][1], a, b1);
            }
        }
        __syncthreads();
    }

    const float bb0 = bias[tn * 4], bb1 = bias[tn * 4 + 1];
    const float bb2 = bias[tn * 4 + 2], bb3 = bias[tn * 4 + 3];
#pragma unroll
    for (int r = 0; r < 8; r++) {
        float4 v;
        v.x = lo32(acc[r][0]) + bb0;
        v.y = hi32(acc[r][0]) + bb1;
        v.z = lo32(acc[r][1]) + bb2;
        v.w = hi32(acc[r][1]) + bb3;
        *(float4*)&out[(row0 + tm * 8 + r) * CH + tn * 4] = v;
    }
}

// ---------------- dummy: shifts ncu's profiled slot onto pt_main --------------------
__global__ void ncu_align_dummy() {}

// ---------------- kernel 2: persistent, fully pipelined attention -------------------
__global__ __launch_bounds__(256, 4) void pt_main(
    const float* __restrict__ xyz, const float* __restrict__ feats,
    const int* __restrict__ nei,
    const float* __restrict__ Wp2, const float* __restrict__ bp2,
    const float* __restrict__ Ww2, const float* __restrict__ bw2,
    float* __restrict__ out) {
    __shared__ __align__(16) float wv_s[KN][CHP];
    __shared__ __align__(16) float vfp_s[KN][CHP];
    __shared__ __align__(16) float part_s[8][KN][17];
    __shared__ __align__(16) float W1s[CS][CHP];
    __shared__ __align__(16) float Ww2s[CS][CS];
    __shared__ __align__(16) float pars_s[6][CH];   // sw, shw, Wp2 r0..r2, bp2
    __shared__ float bw2s[CS];
    __shared__ int   nb_s[2][KN];
    __shared__ float t_s[2][KN][4];
    __shared__ float lgT_s[CS][17];   // [j][k]
    __shared__ float wgt_s[KN][17];   // [k][j]

    const int tid  = threadIdx.x;
    const int wrp  = tid >> 5;
    const int lane = tid & 31;
    const int jb   = lane & 15;
    const int khb  = lane >> 4;
    const int c0   = wrp * 16;
    const int c4   = lane * 4;

    // ---- one-time staging ----
#pragma unroll
    for (int i = 0; i < 2; i++) {
        int f4 = tid + i * 256;
        int row = f4 >> 5;
        int cc = (f4 & 31) * 4;
        *(float4*)&W1s[row][cc] = *(const float4*)&g_W1T[row * CH + cc];
    }
    if (tid < 64) *(float4*)&Ww2s[0][tid * 4] = *(const float4*)&Ww2[tid * 4];
    if (tid >= 64 && tid < 80) bw2s[tid - 64] = bw2[tid - 64];
    {
        int i = tid >> 5;
        int cc = (tid & 31) * 4;
        if (i < 6) {
            const float* src;
            if (i == 0) src = g_sw;
            else if (i == 1) src = g_shw;
            else if (i == 5) src = bp2;
            else src = Wp2 + (i - 2) * CH;
            *(float4*)&pars_s[i][cc] = *(const float4*)&src[cc];
        }
    }

    // ---- prologue: first point ----
    int n = blockIdx.x;
    if (tid < KN) {
        int nb = nei[n * KN + tid];
        nb_s[0][tid] = nb;
        float xc = xyz[n * 3], yc = xyz[n * 3 + 1], zc = xyz[n * 3 + 2];
        float d0 = xyz[nb * 3] - xc, d1 = xyz[nb * 3 + 1] - yc, d2 = xyz[nb * 3 + 2] - zc;
#pragma unroll
        for (int o = 0; o < 3; o++) {
            float v = d0 * g_Wp1f[o] + d1 * g_Wp1f[3 + o] + d2 * g_Wp1f[6 + o] + g_bp1f[o];
            t_s[0][tid][o] = fmaxf(v, 0.0f);
        }
    }
    __syncthreads();

    float4 kf0, vf0, kf1, vf1, q4;
    {
        int nbA = nb_s[0][wrp], nbB = nb_s[0][wrp + 8];
        kf0 = *(const float4*)&g_k[nbA * CH + c4];
        vf0 = *(const float4*)&g_v[nbA * CH + c4];
        kf1 = *(const float4*)&g_k[nbB * CH + c4];
        vf1 = *(const float4*)&g_v[nbB * CH + c4];
        q4  = *(const float4*)&g_q[n * CH + c4];
    }
    int nb16 = 0;
    if (tid < KN && n + GRIDX < NPTS) nb16 = nei[(n + GRIDX) * KN + tid];
    int buf = 0;

    while (true) {
        const int n_next = n + GRIDX;
        const bool has_next = (n_next < NPTS);
        float xcn, ycn, zcn, xnn, ynn, znn;

        // ---- phase A: pure compute from prefetched regs; issue xyz loads for n+1 ----
        {
            const float4 sw4 = *(const float4*)&pars_s[0][c4];
            const float4 sh4 = *(const float4*)&pars_s[1][c4];
            const float4 wpa = *(const float4*)&pars_s[2][c4];
            const float4 wpb = *(const float4*)&pars_s[3][c4];
            const float4 wpc = *(const float4*)&pars_s[4][c4];
            const float4 bp4 = *(const float4*)&pars_s[5][c4];
#pragma unroll
            for (int it = 0; it < 2; it++) {
                const int k = wrp + it * 8;
                const float4 kf = it ? kf1 : kf0;
                const float4 vf = it ? vf1 : vf0;
                const float t0 = t_s[buf][k][0], t1 = t_s[buf][k][1], t2 = t_s[buf][k][2];
                float4 pv, wv, vp;
                pv.x = t0 * wpa.x + t1 * wpb.x + t2 * wpc.x + bp4.x;
                pv.y = t0 * wpa.y + t1 * wpb.y + t2 * wpc.y + bp4.y;
                pv.z = t0 * wpa.z + t1 * wpb.z + t2 * wpc.z + bp4.z;
                pv.w = t0 * wpa.w + t1 * wpb.w + t2 * wpc.w + bp4.w;
                wv.x = fmaxf((kf.x - q4.x + pv.x) * sw4.x + sh4.x, 0.0f);
                wv.y = fmaxf((kf.y - q4.y + pv.y) * sw4.y + sh4.y, 0.0f);
                wv.z = fmaxf((kf.z - q4.z + pv.z) * sw4.z + sh4.z, 0.0f);
                wv.w = fmaxf((kf.w - q4.w + pv.w) * sw4.w + sh4.w, 0.0f);
                vp.x = vf.x + pv.x;
                vp.y = vf.y + pv.y;
                vp.z = vf.z + pv.z;
                vp.w = vf.w + pv.w;
                *(float4*)&wv_s[k][c4]  = wv;
                *(float4*)&vfp_s[k][c4] = vp;
            }
        }
        if (tid < KN && has_next) {
            nb_s[buf ^ 1][tid] = nb16;
            xcn = xyz[n_next * 3]; ycn = xyz[n_next * 3 + 1]; zcn = xyz[n_next * 3 + 2];
            xnn = xyz[nb16 * 3];   ynn = xyz[nb16 * 3 + 1];   znn = xyz[nb16 * 3 + 2];
        }
        __syncthreads();

        // ---- phase B: split-K partials; issue nei load for n+2 ----
        {
            const ulonglong2* w1p = (const ulonglong2*)&W1s[jb][c0];
            const ulonglong2 w1a = w1p[0], w1b = w1p[1], w1c = w1p[2], w1d = w1p[3];
#pragma unroll
            for (int i = 0; i < 8; i++) {
                const int k = i * 2 + khb;
                const ulonglong2* vp = (const ulonglong2*)&wv_s[k][c0];
                ulonglong2 va = vp[0], vb = vp[1], vc = vp[2], vd = vp[3];
                unsigned long long acc = 0ULL;
                ffma2(acc, va.x, w1a.x);
                ffma2(acc, va.y, w1a.y);
                ffma2(acc, vb.x, w1b.x);
                ffma2(acc, vb.y, w1b.y);
                ffma2(acc, vc.x, w1c.x);
                ffma2(acc, vc.y, w1c.y);
                ffma2(acc, vd.x, w1d.x);
                ffma2(acc, vd.y, w1d.y);
                part_s[wrp][k][jb] = lo32(acc) + hi32(acc);
            }
        }
        int nb16_next = 0;
        if (tid < KN && n + 2 * GRIDX < NPTS) nb16_next = nei[(n + 2 * GRIDX) * KN + tid];
        __syncthreads();

        // ---- reduce + relu + logits (shfl), store transposed ----
        {
            const int kk = tid >> 4;
            const int jj = tid & 15;
            float h = g_b1f[jj];
#pragma unroll
            for (int w = 0; w < 8; w++) h += part_s[w][kk][jj];
            h = fmaxf(h, 0.0f);
            float lg = bw2s[jj];
#pragma unroll
            for (int j2 = 0; j2 < CS; j2++)
                lg += __shfl_sync(0xffffffffu, h, j2, 16) * Ww2s[j2][jj];
            lgT_s[jj][kk] = lg;
        }
        __syncthreads();

        // ---- softmax (all 16 half-warps) + next-point gather prefetch + t(n+1) ----
        float4 kf0n, vf0n, kf1n, vf1n, q4n;
        if (has_next) {
            int nbA = nb_s[buf ^ 1][wrp], nbB = nb_s[buf ^ 1][wrp + 8];
            kf0n = *(const float4*)&g_k[nbA * CH + c4];
            vf0n = *(const float4*)&g_v[nbA * CH + c4];
            kf1n = *(const float4*)&g_k[nbB * CH + c4];
            vf1n = *(const float4*)&g_v[nbB * CH + c4];
            q4n  = *(const float4*)&g_q[n_next * CH + c4];
        }
        {
            const int j = tid >> 4;
            const int k = tid & 15;
            float v = lgT_s[j][k];
            float m = v;
#pragma unroll
            for (int d = 1; d < 16; d <<= 1)
                m = fmaxf(m, __shfl_xor_sync(0xffffffffu, m, d, 16));
            float e = __expf(v - m);
            float s = e;
#pragma unroll
            for (int d = 1; d < 16; d <<= 1)
                s += __shfl_xor_sync(0xffffffffu, s, d, 16);
            wgt_s[k][j] = e * (1.0f / s);
        }
        if (tid < KN && has_next) {
            float d0 = xnn - xcn, d1 = ynn - ycn, d2 = znn - zcn;
#pragma unroll
            for (int o = 0; o < 3; o++) {
                float v = d0 * g_Wp1f[o] + d1 * g_Wp1f[3 + o] + d2 * g_Wp1f[6 + o] + g_bp1f[o];
                t_s[buf ^ 1][tid][o] = fmaxf(v, 0.0f);
            }
        }
        __syncthreads();

        // ---- phase D: grouped aggregation + residual + leaky_relu ----
        if (tid < CH) {
            const int c = tid;
            const int jj = c & 15;
            float acc = 0.0f;
#pragma unroll
            for (int k = 0; k < KN; k++)
                acc += vfp_s[k][c] * wgt_s[k][jj];
            float v = acc + feats[n * CH + c];
            out[n * CH + c] = (v > 0.0f) ? v : 0.1f * v;
        }

        if (!has_next) break;
        n = n_next;
        buf ^= 1;
        kf0 = kf0n; vf0 = vf0n; kf1 = kf1n; vf1 = vf1n; q4 = q4n;
        nb16 = nb16_next;
        __syncthreads();   // protect wv_s/vfp_s/wgt_s reuse by next iteration
    }
}

// ---------------- launch ------------------------------------------------------------
extern "C" void kernel_launch(void* const* d_in, const int* in_sizes, int n_in,
                              void* d_out, int out_size) {
    const float* xyz   = (const float*)d_in[0];
    const float* feats = (const float*)d_in[1];
    const int*   nei   = (const int*)d_in[2];
    const float* Wq = (const float*)d_in[3];
    const float* bq = (const float*)d_in[4];
    const float* Wk = (const float*)d_in[5];
    const float* bk = (const float*)d_in[6];
    const float* Wv = (const float*)d_in[7];
    const float* bv = (const float*)d_in[8];
    const float* Wp1 = (const float*)d_in[9];
    const float* bp1 = (const float*)d_in[10];
    const float* p_gamma = (const float*)d_in[11];
    const float* p_beta  = (const float*)d_in[12];
    const float* p_mean  = (const float*)d_in[13];
    const float* p_var   = (const float*)d_in[14];
    const float* Wp2 = (const float*)d_in[15];
    const float* bp2 = (const float*)d_in[16];
    const float* w_gamma = (const float*)d_in[17];
    const float* w_beta  = (const float*)d_in[18];
    const float* w_mean  = (const float*)d_in[19];
    const float* w_var   = (const float*)d_in[20];
    const float* Ww1 = (const float*)d_in[21];
    const float* bw1 = (const float*)d_in[22];
    const float* w1_gamma = (const float*)d_in[23];
    const float* w1_beta  = (const float*)d_in[24];
    const float* w1_mean  = (const float*)d_in[25];
    const float* w1_var   = (const float*)d_in[26];
    const float* Ww2 = (const float*)d_in[27];
    const float* bw2 = (const float*)d_in[28];
    float* out = (float*)d_out;

    prep_kernel<<<1, 256>>>(w_gamma, w_beta, w_mean, w_var, Ww1, bw1, w1_gamma,
                            w1_beta, w1_mean, w1_var, Wp1, bp1, p_gamma, p_beta,
                            p_mean, p_var);
    qkv_gemm<<<dim3(625, 3), 256>>>(feats, Wq, bq, Wk, bk, Wv, bv);
    ncu_align_dummy<<<1, 32>>>();
    pt_main<<<GRIDX, 256>>>(xyz, feats, nei, Wp2, bp2, Ww2, bw2, out);
}

// round 10
// speedup vs baseline: 1.1015x; 1.1015x over previous
#include <cuda_runtime.h>

#define NPTS 40000
#define KN 16
#define CH 128
#define CS 16          // C / S
#define CHP 132        // padded row stride (528 B)
#define GRIDX 592      // 4 blocks/SM * 148 SMs, persistent
#define EPSBN 1e-5f

// ---------------- scratch (no allocation allowed -> __device__ globals) -------------
__device__ float g_q[NPTS * CH];
__device__ float g_k[NPTS * CH];
__device__ float g_v[NPTS * CH];
__device__ float g_W1T[CS * CH];   // folded (Ww1 * s1)^T
__device__ float g_sw[CH];
__device__ float g_shw[CH];
__device__ float g_b1f[CS];
__device__ float g_Wp1f[9];
__device__ float g_bp1f[3];

__device__ __forceinline__ void ffma2(unsigned long long& d,
                                      unsigned long long a,
                                      unsigned long long b) {
    asm("fma.rn.f32x2 %0, %1, %2, %0;" : "+l"(d) : "l"(a), "l"(b));
}
__device__ __forceinline__ unsigned long long dup2(float f) {
    unsigned int u = __float_as_uint(f);
    return ((unsigned long long)u << 32) | (unsigned long long)u;
}
__device__ __forceinline__ float lo32(unsigned long long v) {
    return __uint_as_float((unsigned int)v);
}
__device__ __forceinline__ float hi32(unsigned long long v) {
    return __uint_as_float((unsigned int)(v >> 32));
}

// ---------------- kernel 0: fold BN params -----------------------------------------
__global__ void prep_kernel(const float* __restrict__ w_gamma, const float* __restrict__ w_beta,
                            const float* __restrict__ w_mean, const float* __restrict__ w_var,
                            const float* __restrict__ Ww1, const float* __restrict__ bw1,
                            const float* __restrict__ w1_gamma, const float* __restrict__ w1_beta,
                            const float* __restrict__ w1_mean, const float* __restrict__ w1_var,
                            const float* __restrict__ Wp1, const float* __restrict__ bp1,
                            const float* __restrict__ p_gamma, const float* __restrict__ p_beta,
                            const float* __restrict__ p_mean, const float* __restrict__ p_var) {
    int t = threadIdx.x;
    if (t < CH) {
        float s = w_gamma[t] * rsqrtf(w_var[t] + EPSBN);
        g_sw[t] = s;
        g_shw[t] = w_beta[t] - w_mean[t] * s;
    }
    for (int idx = t; idx < CS * CH; idx += blockDim.x) {
        int j = idx / CH, c = idx % CH;
        float s1 = w1_gamma[j] * rsqrtf(w1_var[j] + EPSBN);
        g_W1T[idx] = Ww1[c * CS + j] * s1;
    }
    if (t < CS) {
        float s1 = w1_gamma[t] * rsqrtf(w1_var[t] + EPSBN);
        g_b1f[t] = (bw1[t] - w1_mean[t]) * s1 + w1_beta[t];
    }
    if (t < 9) {
        int o = t % 3;
        float sp = p_gamma[o] * rsqrtf(p_var[o] + EPSBN);
        g_Wp1f[t] = Wp1[t] * sp;
    }
    if (t < 3) {
        float sp = p_gamma[t] * rsqrtf(p_var[t] + EPSBN);
        g_bp1f[t] = (bp1[t] - p_mean[t]) * sp + p_beta[t];
    }
}

// ---------------- kernel 1: fused q/k/v GEMM (unchanged) ----------------------------
__global__ __launch_bounds__(256, 2) void qkv_gemm(
    const float* __restrict__ x,
    const float* __restrict__ Wq, const float* __restrict__ bq,
    const float* __restrict__ Wk, const float* __restrict__ bk,
    const float* __restrict__ Wv, const float* __restrict__ bv) {
    const float* W;
    const float* bias;
    float* out;
    if (blockIdx.y == 0)      { W = Wq; bias = bq; out = g_q; }
    else if (blockIdx.y == 1) { W = Wk; bias = bk; out = g_k; }
    else                      { W = Wv; bias = bv; out = g_v; }

    __shared__ __align__(16) unsigned long long A2s[16][64];
    __shared__ __align__(16) float Bs[16][128];

    const int tid = threadIdx.x;
    const int tm = tid >> 5;
    const int tn = tid & 31;
    const int row0 = blockIdx.x * 64;

    unsigned long long acc[8][2];
#pragma unroll
    for (int r = 0; r < 8; r++) { acc[r][0] = 0ULL; acc[r][1] = 0ULL; }

    for (int kt = 0; kt < 8; kt++) {
        const int k0 = kt * 16;
        {
            int ar = tid >> 2;
            int ac = (tid & 3) * 4;
            float4 av = *(const float4*)&x[(row0 + ar) * CH + k0 + ac];
            A2s[ac + 0][ar] = dup2(av.x);
            A2s[ac + 1][ar] = dup2(av.y);
            A2s[ac + 2][ar] = dup2(av.z);
            A2s[ac + 3][ar] = dup2(av.w);
        }
#pragma unroll
        for (int i = 0; i < 2; i++) {
            int f4 = tid * 2 + i;
            int bkr = f4 >> 5;
            int bc = (f4 & 31) * 4;
            *(float4*)&Bs[bkr][bc] = *(const float4*)&W[(k0 + bkr) * CH + bc];
        }
        __syncthreads();
#pragma unroll
        for (int kk = 0; kk < 16; kk++) {
            unsigned long long b0 = *(const unsigned long long*)&Bs[kk][tn * 4];
            unsigned long long b1 = *(const unsigned long long*)&Bs[kk][tn * 4 + 2];
#pragma unroll
            for (int r = 0; r < 8; r++) {
                unsigned long long a = A2s[kk][tm * 8 + r];
                ffma2(acc[r][0], a, b0);
                ffma2(acc[r][1], a, b1);
            }
        }
        __syncthreads();
    }

    const float bb0 = bias[tn * 4], bb1 = bias[tn * 4 + 1];
    const float bb2 = bias[tn * 4 + 2], bb3 = bias[tn * 4 + 3];
#pragma unroll
    for (int r = 0; r < 8; r++) {
        float4 v;
        v.x = lo32(acc[r][0]) + bb0;
        v.y = hi32(acc[r][0]) + bb1;
        v.z = lo32(acc[r][1]) + bb2;
        v.w = hi32(acc[r][1]) + bb3;
        *(float4*)&out[(row0 + tm * 8 + r) * CH + tn * 4] = v;
    }
}

// ---------------- dummy: keeps ncu's profiled slot on pt_main -----------------------
__global__ void ncu_align_dummy() {}

// ---------------- kernel 2: persistent attention, L1tex-traffic-minimized -----------
__global__ __launch_bounds__(256, 4) void pt_main(
    const float* __restrict__ xyz, const float* __restrict__ feats,
    const int* __restrict__ nei,
    const float* __restrict__ Wp2, const float* __restrict__ bp2,
    const float* __restrict__ Ww2, const float* __restrict__ bw2,
    float* __restrict__ out) {
    __shared__ __align__(16) float wv_s[KN][CHP];
    __shared__ __align__(16) float agg_s[8][CHP];     // per-warp pre-weighted partials
    __shared__ __align__(16) float part_s[8][KN][17]; // split-K partials
    __shared__ __align__(16) float W1s[CS][CHP];
    __shared__ __align__(16) float Ww2s[CS][CS];
    __shared__ __align__(16) float pars_s[6][CH];     // sw, shw, Wp2 r0..r2, bp2
    __shared__ float bw2s[CS];
    __shared__ int   nb_s[2][KN];
    __shared__ float t_s[2][KN][4];
    __shared__ float lgT_s[CS][17];                   // [j][k]
    __shared__ __align__(16) float wgt_s[KN][CS];     // [k][j], 16-float rows (f4-aligned)

    const int tid  = threadIdx.x;
    const int wrp  = tid >> 5;
    const int lane = tid & 31;
    const int jb   = lane & 15;
    const int khb  = lane >> 4;
    const int c0   = wrp * 16;
    const int c4   = lane * 4;

    // ---- one-time staging ----
#pragma unroll
    for (int i = 0; i < 2; i++) {
        int f4 = tid + i * 256;
        int row = f4 >> 5;
        int cc = (f4 & 31) * 4;
        *(float4*)&W1s[row][cc] = *(const float4*)&g_W1T[row * CH + cc];
    }
    if (tid < 64) *(float4*)&Ww2s[0][tid * 4] = *(const float4*)&Ww2[tid * 4];
    if (tid >= 64 && tid < 80) bw2s[tid - 64] = bw2[tid - 64];
    {
        int i = tid >> 5;
        int cc = (tid & 31) * 4;
        if (i < 6) {
            const float* src;
            if (i == 0) src = g_sw;
            else if (i == 1) src = g_shw;
            else if (i == 5) src = bp2;
            else src = Wp2 + (i - 2) * CH;
            *(float4*)&pars_s[i][cc] = *(const float4*)&src[cc];
        }
    }

    // ---- prologue: first point ----
    int n = blockIdx.x;
    if (tid < KN) {
        int nb = nei[n * KN + tid];
        nb_s[0][tid] = nb;
        float xc = xyz[n * 3], yc = xyz[n * 3 + 1], zc = xyz[n * 3 + 2];
        float d0 = xyz[nb * 3] - xc, d1 = xyz[nb * 3 + 1] - yc, d2 = xyz[nb * 3 + 2] - zc;
#pragma unroll
        for (int o = 0; o < 3; o++) {
            float v = d0 * g_Wp1f[o] + d1 * g_Wp1f[3 + o] + d2 * g_Wp1f[6 + o] + g_bp1f[o];
            t_s[0][tid][o] = fmaxf(v, 0.0f);
        }
    }
    int nb16 = 0;
    if (tid < KN && n + GRIDX < NPTS) nb16 = nei[(n + GRIDX) * KN + tid];
    __syncthreads();

    int buf = 0;
    while (true) {
        const int n_next = n + GRIDX;
        const bool has_next = (n_next < NPTS);
        float xcn, ycn, zcn, xnn, ynn, znn;
        float4 vp0, vp1;

        // ---- phase A: gather + compute; wv -> smem, vfp -> REGS ----
        {
            const float4 q4  = *(const float4*)&g_q[n * CH + c4];
            const int nbA = nb_s[buf][wrp];
            const int nbB = nb_s[buf][wrp + 8];
            const float4 kfA = *(const float4*)&g_k[nbA * CH + c4];
            const float4 vfA = *(const float4*)&g_v[nbA * CH + c4];
            const float4 kfB = *(const float4*)&g_k[nbB * CH + c4];
            const float4 vfB = *(const float4*)&g_v[nbB * CH + c4];
            const float4 sw4 = *(const float4*)&pars_s[0][c4];
            const float4 sh4 = *(const float4*)&pars_s[1][c4];
            const float4 wpa = *(const float4*)&pars_s[2][c4];
            const float4 wpb = *(const float4*)&pars_s[3][c4];
            const float4 wpc = *(const float4*)&pars_s[4][c4];
            const float4 bp4 = *(const float4*)&pars_s[5][c4];
            {
                const int k = wrp;
                const float t0 = t_s[buf][k][0], t1 = t_s[buf][k][1], t2 = t_s[buf][k][2];
                float4 pv, wv;
                pv.x = t0 * wpa.x + t1 * wpb.x + t2 * wpc.x + bp4.x;
                pv.y = t0 * wpa.y + t1 * wpb.y + t2 * wpc.y + bp4.y;
                pv.z = t0 * wpa.z + t1 * wpb.z + t2 * wpc.z + bp4.z;
                pv.w = t0 * wpa.w + t1 * wpb.w + t2 * wpc.w + bp4.w;
                wv.x = fmaxf((kfA.x - q4.x + pv.x) * sw4.x + sh4.x, 0.0f);
                wv.y = fmaxf((kfA.y - q4.y + pv.y) * sw4.y + sh4.y, 0.0f);
                wv.z = fmaxf((kfA.z - q4.z + pv.z) * sw4.z + sh4.z, 0.0f);
                wv.w = fmaxf((kfA.w - q4.w + pv.w) * sw4.w + sh4.w, 0.0f);
                vp0.x = vfA.x + pv.x; vp0.y = vfA.y + pv.y;
                vp0.z = vfA.z + pv.z; vp0.w = vfA.w + pv.w;
                *(float4*)&wv_s[k][c4] = wv;
            }
            {
                const int k = wrp + 8;
                const float t0 = t_s[buf][k][0], t1 = t_s[buf][k][1], t2 = t_s[buf][k][2];
                float4 pv, wv;
                pv.x = t0 * wpa.x + t1 * wpb.x + t2 * wpc.x + bp4.x;
                pv.y = t0 * wpa.y + t1 * wpb.y + t2 * wpc.y + bp4.y;
                pv.z = t0 * wpa.z + t1 * wpb.z + t2 * wpc.z + bp4.z;
                pv.w = t0 * wpa.w + t1 * wpb.w + t2 * wpc.w + bp4.w;
                wv.x = fmaxf((kfB.x - q4.x + pv.x) * sw4.x + sh4.x, 0.0f);
                wv.y = fmaxf((kfB.y - q4.y + pv.y) * sw4.y + sh4.y, 0.0f);
                wv.z = fmaxf((kfB.z - q4.z + pv.z) * sw4.z + sh4.z, 0.0f);
                wv.w = fmaxf((kfB.w - q4.w + pv.w) * sw4.w + sh4.w, 0.0f);
                vp1.x = vfB.x + pv.x; vp1.y = vfB.y + pv.y;
                vp1.z = vfB.z + pv.z; vp1.w = vfB.w + pv.w;
                *(float4*)&wv_s[k][c4] = wv;
            }
        }
        if (tid < KN && has_next) {
            nb_s[buf ^ 1][tid] = nb16;
            xcn = xyz[n_next * 3]; ycn = xyz[n_next * 3 + 1]; zcn = xyz[n_next * 3 + 2];
            xnn = xyz[nb16 * 3];   ynn = xyz[nb16 * 3 + 1];   znn = xyz[nb16 * 3 + 2];
        }
        __syncthreads();

        // ---- phase B: split-K partials; prefetch nei(n+2) ----
        {
            const ulonglong2* w1p = (const ulonglong2*)&W1s[jb][c0];
            const ulonglong2 w1a = w1p[0], w1b = w1p[1], w1c = w1p[2], w1d = w1p[3];
#pragma unroll
            for (int i = 0; i < 8; i++) {
                const int k = i * 2 + khb;
                const ulonglong2* vp = (const ulonglong2*)&wv_s[k][c0];
                ulonglong2 va = vp[0], vb = vp[1], vc = vp[2], vd = vp[3];
                unsigned long long acc = 0ULL;
                ffma2(acc, va.x, w1a.x);
                ffma2(acc, va.y, w1a.y);
                ffma2(acc, vb.x, w1b.x);
                ffma2(acc, vb.y, w1b.y);
                ffma2(acc, vc.x, w1c.x);
                ffma2(acc, vc.y, w1c.y);
                ffma2(acc, vd.x, w1d.x);
                ffma2(acc, vd.y, w1d.y);
                part_s[wrp][k][jb] = lo32(acc) + hi32(acc);
            }
        }
        int nb16_next = 0;
        if (tid < KN && n + 2 * GRIDX < NPTS) nb16_next = nei[(n + 2 * GRIDX) * KN + tid];
        __syncthreads();

        // ---- reduce + relu + logits (shfl), store transposed ----
        {
            const int kk = tid >> 4;
            const int jj = tid & 15;
            float h = g_b1f[jj];
#pragma unroll
            for (int w = 0; w < 8; w++) h += part_s[w][kk][jj];
            h = fmaxf(h, 0.0f);
            float lg = bw2s[jj];
#pragma unroll
            for (int j2 = 0; j2 < CS; j2++)
                lg += __shfl_sync(0xffffffffu, h, j2, 16) * Ww2s[j2][jj];
            lgT_s[jj][kk] = lg;
        }
        __syncthreads();

        // ---- softmax (all 16 half-warps) + t(n+1) from regs ----
        {
            const int j = tid >> 4;
            const int k = tid & 15;
            float v = lgT_s[j][k];
            float m = v;
#pragma unroll
            for (int d = 1; d < 16; d <<= 1)
                m = fmaxf(m, __shfl_xor_sync(0xffffffffu, m, d, 16));
            float e = __expf(v - m);
            float s = e;
#pragma unroll
            for (int d = 1; d < 16; d <<= 1)
                s += __shfl_xor_sync(0xffffffffu, s, d, 16);
            wgt_s[k][j] = e * (1.0f / s);
        }
        if (tid < KN && has_next) {
            float d0 = xnn - xcn, d1 = ynn - ycn, d2 = znn - zcn;
#pragma unroll
            for (int o = 0; o < 3; o++) {
                float v = d0 * g_Wp1f[o] + d1 * g_Wp1f[3 + o] + d2 * g_Wp1f[6 + o] + g_bp1f[o];
                t_s[buf ^ 1][tid][o] = fmaxf(v, 0.0f);
            }
        }
        __syncthreads();

        // ---- phase D-1: in-warp pre-weighted aggregation (vfp never hit smem) ----
        {
            const int jq = c4 & 15;   // 0,4,8,12
            const float4 wA = *(const float4*)&wgt_s[wrp][jq];
            const float4 wB = *(const float4*)&wgt_s[wrp + 8][jq];
            float4 pa;
            pa.x = wA.x * vp0.x + wB.x * vp1.x;
            pa.y = wA.y * vp0.y + wB.y * vp1.y;
            pa.z = wA.z * vp0.z + wB.z * vp1.z;
            pa.w = wA.w * vp0.w + wB.w * vp1.w;
            *(float4*)&agg_s[wrp][c4] = pa;
        }
        __syncthreads();

        // ---- phase D-2: 8-way cross-warp sum + residual + leaky_relu ----
        if (tid < CH) {
            float acc = 0.0f;
#pragma unroll
            for (int w = 0; w < 8; w++)
                acc += agg_s[w][tid];
            float v = acc + feats[n * CH + tid];
            out[n * CH + tid] = (v > 0.0f) ? v : 0.1f * v;
        }

        if (!has_next) break;
        n = n_next;
        buf ^= 1;
        nb16 = nb16_next;
        // no trailing barrier: next phase A writes only wv_s, disjoint from D-2 reads
    }
}

// ---------------- launch ------------------------------------------------------------
extern "C" void kernel_launch(void* const* d_in, const int* in_sizes, int n_in,
                              void* d_out, int out_size) {
    const float* xyz   = (const float*)d_in[0];
    const float* feats = (const float*)d_in[1];
    const int*   nei   = (const int*)d_in[2];
    const float* Wq = (const float*)d_in[3];
    const float* bq = (const float*)d_in[4];
    const float* Wk = (const float*)d_in[5];
    const float* bk = (const float*)d_in[6];
    const float* Wv = (const float*)d_in[7];
    const float* bv = (const float*)d_in[8];
    const float* Wp1 = (const float*)d_in[9];
    const float* bp1 = (const float*)d_in[10];
    const float* p_gamma = (const float*)d_in[11];
    const float* p_beta  = (const float*)d_in[12];
    const float* p_mean  = (const float*)d_in[13];
    const float* p_var   = (const float*)d_in[14];
    const float* Wp2 = (const float*)d_in[15];
    const float* bp2 = (const float*)d_in[16];
    const float* w_gamma = (const float*)d_in[17];
    const float* w_beta  = (const float*)d_in[18];
    const float* w_mean  = (const float*)d_in[19];
    const float* w_var   = (const float*)d_in[20];
    const float* Ww1 = (const float*)d_in[21];
    const float* bw1 = (const float*)d_in[22];
    const float* w1_gamma = (const float*)d_in[23];
    const float* w1_beta  = (const float*)d_in[24];
    const float* w1_mean  = (const float*)d_in[25];
    const float* w1_var   = (const float*)d_in[26];
    const float* Ww2 = (const float*)d_in[27];
    const float* bw2 = (const float*)d_in[28];
    float* out = (float*)d_out;

    prep_kernel<<<1, 256>>>(w_gamma, w_beta, w_mean, w_var, Ww1, bw1, w1_gamma,
                            w1_beta, w1_mean, w1_var, Wp1, bp1, p_gamma, p_beta,
                            p_mean, p_var);
    qkv_gemm<<<dim3(625, 3), 256>>>(feats, Wq, bq, Wk, bk, Wv, bv);
    ncu_align_dummy<<<1, 32>>>();
    pt_main<<<GRIDX, 256>>>(xyz, feats, nei, Wp2, bp2, Ww2, bw2, out);
}

// round 14
// speedup vs baseline: 1.1373x; 1.0324x over previous
#include <cuda_runtime.h>

#define NPTS 40000
#define KN 16
#define CH 128
#define CS 16          // C / S
#define CHP 132        // padded row stride (528 B)
#define GRIDX 592      // 4 blocks/SM * 148 SMs, persistent
#define EPSBN 1e-5f

// ---------------- scratch (no allocation allowed -> __device__ globals) -------------
__device__ float g_q[NPTS * CH];
__device__ float g_k[NPTS * CH];
__device__ float g_v[NPTS * CH];
__device__ float g_W1T[CS * CH];   // folded (Ww1 * s1)^T
__device__ float g_sw[CH];
__device__ float g_shw[CH];
__device__ float g_b1f[CS];
__device__ float g_Wp1f[9];
__device__ float g_bp1f[3];

__device__ __forceinline__ void ffma2(unsigned long long& d,
                                      unsigned long long a,
                                      unsigned long long b) {
    asm("fma.rn.f32x2 %0, %1, %2, %0;" : "+l"(d) : "l"(a), "l"(b));
}
__device__ __forceinline__ unsigned long long dup2(float f) {
    unsigned int u = __float_as_uint(f);
    return ((unsigned long long)u << 32) | (unsigned long long)u;
}
__device__ __forceinline__ float lo32(unsigned long long v) {
    return __uint_as_float((unsigned int)v);
}
__device__ __forceinline__ float hi32(unsigned long long v) {
    return __uint_as_float((unsigned int)(v >> 32));
}

// ---------------- kernel 0: fold BN params -----------------------------------------
__global__ void prep_kernel(const float* __restrict__ w_gamma, const float* __restrict__ w_beta,
                            const float* __restrict__ w_mean, const float* __restrict__ w_var,
                            const float* __restrict__ Ww1, const float* __restrict__ bw1,
                            const float* __restrict__ w1_gamma, const float* __restrict__ w1_beta,
                            const float* __restrict__ w1_mean, const float* __restrict__ w1_var,
                            const float* __restrict__ Wp1, const float* __restrict__ bp1,
                            const float* __restrict__ p_gamma, const float* __restrict__ p_beta,
                            const float* __restrict__ p_mean, const float* __restrict__ p_var) {
    int t = threadIdx.x;
    if (t < CH) {
        float s = w_gamma[t] * rsqrtf(w_var[t] + EPSBN);
        g_sw[t] = s;
        g_shw[t] = w_beta[t] - w_mean[t] * s;
    }
    for (int idx = t; idx < CS * CH; idx += blockDim.x) {
        int j = idx / CH, c = idx % CH;
        float s1 = w1_gamma[j] * rsqrtf(w1_var[j] + EPSBN);
        g_W1T[idx] = Ww1[c * CS + j] * s1;
    }
    if (t < CS) {
        float s1 = w1_gamma[t] * rsqrtf(w1_var[t] + EPSBN);
        g_b1f[t] = (bw1[t] - w1_mean[t]) * s1 + w1_beta[t];
    }
    if (t < 9) {
        int o = t % 3;
        float sp = p_gamma[o] * rsqrtf(p_var[o] + EPSBN);
        g_Wp1f[t] = Wp1[t] * sp;
    }
    if (t < 3) {
        float sp = p_gamma[t] * rsqrtf(p_var[t] + EPSBN);
        g_bp1f[t] = (bp1[t] - p_mean[t]) * sp + p_beta[t];
    }
}

// ---------------- kernel 1: FUSED q+k+v GEMM (A loaded once, 3 B mats) --------------
// BM=32, BN=128, BK=16. 256 threads: tm=tid>>5 (4 rows each), tn=tid&31 (4 cols).
// Per kk: 4 A-broadcast LDS + 6 B LDS -> 24 FFMA2 (3 mats x 4 rows x 2 f32x2).
__global__ __launch_bounds__(256, 2) void qkv_gemm(
    const float* __restrict__ x,
    const float* __restrict__ Wq, const float* __restrict__ bq,
    const float* __restrict__ Wk, const float* __restrict__ bk,
    const float* __restrict__ Wv, const float* __restrict__ bv) {
    __shared__ __align__(16) unsigned long long A2s[16][33];  // A dup'd, padded
    __shared__ __align__(16) float Bs[3][16][128];

    const int tid = threadIdx.x;
    const int tm = tid >> 5;   // 0..7 -> rows tm*4..tm*4+3
    const int tn = tid & 31;   // 0..31 -> cols tn*4..tn*4+3
    const int row0 = blockIdx.x * 32;

    const float* Wmat[3] = {Wq, Wk, Wv};

    unsigned long long acc[3][4][2];
#pragma unroll
    for (int m = 0; m < 3; m++)
#pragma unroll
        for (int r = 0; r < 4; r++) { acc[m][r][0] = 0ULL; acc[m][r][1] = 0ULL; }

    for (int kt = 0; kt < 8; kt++) {
        const int k0 = kt * 16;
        // A tile 32x16: threads 0..127 load one float4 each, store dup'd+transposed
        if (tid < 128) {
            int ar = tid >> 2;
            int ac = (tid & 3) * 4;
            float4 av = *(const float4*)&x[(row0 + ar) * CH + k0 + ac];
            A2s[ac + 0][ar] = dup2(av.x);
            A2s[ac + 1][ar] = dup2(av.y);
            A2s[ac + 2][ar] = dup2(av.z);
            A2s[ac + 3][ar] = dup2(av.w);
        }
        // B tiles 3x16x128: 1536 float4 / 256 threads = 6 each
#pragma unroll
        for (int i = 0; i < 6; i++) {
            int f4 = tid + i * 256;
            int m = f4 >> 9;
            int rem = f4 & 511;
            int kkr = rem >> 5;
            int bc = (rem & 31) * 4;
            *(float4*)&Bs[m][kkr][bc] = *(const float4*)&Wmat[m][(k0 + kkr) * CH + bc];
        }
        __syncthreads();
#pragma unroll
        for (int kk = 0; kk < 16; kk++) {
            unsigned long long a0 = A2s[kk][tm * 4 + 0];
            unsigned long long a1 = A2s[kk][tm * 4 + 1];
            unsigned long long a2 = A2s[kk][tm * 4 + 2];
            unsigned long long a3 = A2s[kk][tm * 4 + 3];
#pragma unroll
            for (int m = 0; m < 3; m++) {
                unsigned long long b0 = *(const unsigned long long*)&Bs[m][kk][tn * 4];
                unsigned long long b1 = *(const unsigned long long*)&Bs[m][kk][tn * 4 + 2];
                ffma2(acc[m][0][0], a0, b0);
                ffma2(acc[m][0][1], a0, b1);
                ffma2(acc[m][1][0], a1, b0);
                ffma2(acc[m][1][1], a1, b1);
                ffma2(acc[m][2][0], a2, b0);
                ffma2(acc[m][2][1], a2, b1);
                ffma2(acc[m][3][0], a3, b0);
                ffma2(acc[m][3][1], a3, b1);
            }
        }
        __syncthreads();
    }

    float* outp[3] = {g_q, g_k, g_v};
    const float* biasp[3] = {bq, bk, bv};
#pragma unroll
    for (int m = 0; m < 3; m++) {
        const float bb0 = biasp[m][tn * 4],     bb1 = biasp[m][tn * 4 + 1];
        const float bb2 = biasp[m][tn * 4 + 2], bb3 = biasp[m][tn * 4 + 3];
#pragma unroll
        for (int r = 0; r < 4; r++) {
            float4 v;
            v.x = lo32(acc[m][r][0]) + bb0;
            v.y = hi32(acc[m][r][0]) + bb1;
            v.z = lo32(acc[m][r][1]) + bb2;
            v.w = hi32(acc[m][r][1]) + bb3;
            *(float4*)&outp[m][(row0 + tm * 4 + r) * CH + tn * 4] = v;
        }
    }
}

// ---------------- dummy: keeps ncu's profiled slot on pt_main -----------------------
__global__ void ncu_align_dummy() {}

// ---------------- kernel 2: persistent attention (unchanged from R10) ---------------
__global__ __launch_bounds__(256, 4) void pt_main(
    const float* __restrict__ xyz, const float* __restrict__ feats,
    const int* __restrict__ nei,
    const float* __restrict__ Wp2, const float* __restrict__ bp2,
    const float* __restrict__ Ww2, const float* __restrict__ bw2,
    float* __restrict__ out) {
    __shared__ __align__(16) float wv_s[KN][CHP];
    __shared__ __align__(16) float agg_s[8][CHP];
    __shared__ __align__(16) float part_s[8][KN][17];
    __shared__ __align__(16) float W1s[CS][CHP];
    __shared__ __align__(16) float Ww2s[CS][CS];
    __shared__ __align__(16) float pars_s[6][CH];
    __shared__ float bw2s[CS];
    __shared__ int   nb_s[2][KN];
    __shared__ float t_s[2][KN][4];
    __shared__ float lgT_s[CS][17];
    __shared__ __align__(16) float wgt_s[KN][CS];

    const int tid  = threadIdx.x;
    const int wrp  = tid >> 5;
    const int lane = tid & 31;
    const int jb   = lane & 15;
    const int khb  = lane >> 4;
    const int c0   = wrp * 16;
    const int c4   = lane * 4;

#pragma unroll
    for (int i = 0; i < 2; i++) {
        int f4 = tid + i * 256;
        int row = f4 >> 5;
        int cc = (f4 & 31) * 4;
        *(float4*)&W1s[row][cc] = *(const float4*)&g_W1T[row * CH + cc];
    }
    if (tid < 64) *(float4*)&Ww2s[0][tid * 4] = *(const float4*)&Ww2[tid * 4];
    if (tid >= 64 && tid < 80) bw2s[tid - 64] = bw2[tid - 64];
    {
        int i = tid >> 5;
        int cc = (tid & 31) * 4;
        if (i < 6) {
            const float* src;
            if (i == 0) src = g_sw;
            else if (i == 1) src = g_shw;
            else if (i == 5) src = bp2;
            else src = Wp2 + (i - 2) * CH;
            *(float4*)&pars_s[i][cc] = *(const float4*)&src[cc];
        }
    }

    int n = blockIdx.x;
    if (tid < KN) {
        int nb = nei[n * KN + tid];
        nb_s[0][tid] = nb;
        float xc = xyz[n * 3], yc = xyz[n * 3 + 1], zc = xyz[n * 3 + 2];
        float d0 = xyz[nb * 3] - xc, d1 = xyz[nb * 3 + 1] - yc, d2 = xyz[nb * 3 + 2] - zc;
#pragma unroll
        for (int o = 0; o < 3; o++) {
            float v = d0 * g_Wp1f[o] + d1 * g_Wp1f[3 + o] + d2 * g_Wp1f[6 + o] + g_bp1f[o];
            t_s[0][tid][o] = fmaxf(v, 0.0f);
        }
    }
    int nb16 = 0;
    if (tid < KN && n + GRIDX < NPTS) nb16 = nei[(n + GRIDX) * KN + tid];
    __syncthreads();

    int buf = 0;
    while (true) {
        const int n_next = n + GRIDX;
        const bool has_next = (n_next < NPTS);
        float xcn, ycn, zcn, xnn, ynn, znn;
        float4 vp0, vp1;

        // ---- phase A: gather + compute; wv -> smem, vfp -> REGS ----
        {
            const float4 q4  = *(const float4*)&g_q[n * CH + c4];
            const int nbA = nb_s[buf][wrp];
            const int nbB = nb_s[buf][wrp + 8];
            const float4 kfA = *(const float4*)&g_k[nbA * CH + c4];
            const float4 vfA = *(const float4*)&g_v[nbA * CH + c4];
            const float4 kfB = *(const float4*)&g_k[nbB * CH + c4];
            const float4 vfB = *(const float4*)&g_v[nbB * CH + c4];
            const float4 sw4 = *(const float4*)&pars_s[0][c4];
            const float4 sh4 = *(const float4*)&pars_s[1][c4];
            const float4 wpa = *(const float4*)&pars_s[2][c4];
            const float4 wpb = *(const float4*)&pars_s[3][c4];
            const float4 wpc = *(const float4*)&pars_s[4][c4];
            const float4 bp4 = *(const float4*)&pars_s[5][c4];
            {
                const int k = wrp;
                const float t0 = t_s[buf][k][0], t1 = t_s[buf][k][1], t2 = t_s[buf][k][2];
                float4 pv, wv;
                pv.x = t0 * wpa.x + t1 * wpb.x + t2 * wpc.x + bp4.x;
                pv.y = t0 * wpa.y + t1 * wpb.y + t2 * wpc.y + bp4.y;
                pv.z = t0 * wpa.z + t1 * wpb.z + t2 * wpc.z + bp4.z;
                pv.w = t0 * wpa.w + t1 * wpb.w + t2 * wpc.w + bp4.w;
                wv.x = fmaxf((kfA.x - q4.x + pv.x) * sw4.x + sh4.x, 0.0f);
                wv.y = fmaxf((kfA.y - q4.y + pv.y) * sw4.y + sh4.y, 0.0f);
                wv.z = fmaxf((kfA.z - q4.z + pv.z) * sw4.z + sh4.z, 0.0f);
                wv.w = fmaxf((kfA.w - q4.w + pv.w) * sw4.w + sh4.w, 0.0f);
                vp0.x = vfA.x + pv.x; vp0.y = vfA.y + pv.y;
                vp0.z = vfA.z + pv.z; vp0.w = vfA.w + pv.w;
                *(float4*)&wv_s[k][c4] = wv;
            }
            {
                const int k = wrp + 8;
                const float t0 = t_s[buf][k][0], t1 = t_s[buf][k][1], t2 = t_s[buf][k][2];
                float4 pv, wv;
                pv.x = t0 * wpa.x + t1 * wpb.x + t2 * wpc.x + bp4.x;
                pv.y = t0 * wpa.y + t1 * wpb.y + t2 * wpc.y + bp4.y;
                pv.z = t0 * wpa.z + t1 * wpb.z + t2 * wpc.z + bp4.z;
                pv.w = t0 * wpa.w + t1 * wpb.w + t2 * wpc.w + bp4.w;
                wv.x = fmaxf((kfB.x - q4.x + pv.x) * sw4.x + sh4.x, 0.0f);
                wv.y = fmaxf((kfB.y - q4.y + pv.y) * sw4.y + sh4.y, 0.0f);
                wv.z = fmaxf((kfB.z - q4.z + pv.z) * sw4.z + sh4.z, 0.0f);
                wv.w = fmaxf((kfB.w - q4.w + pv.w) * sw4.w + sh4.w, 0.0f);
                vp1.x = vfB.x + pv.x; vp1.y = vfB.y + pv.y;
                vp1.z = vfB.z + pv.z; vp1.w = vfB.w + pv.w;
                *(float4*)&wv_s[k][c4] = wv;
            }
        }
        if (tid < KN && has_next) {
            nb_s[buf ^ 1][tid] = nb16;
            xcn = xyz[n_next * 3]; ycn = xyz[n_next * 3 + 1]; zcn = xyz[n_next * 3 + 2];
            xnn = xyz[nb16 * 3];   ynn = xyz[nb16 * 3 + 1];   znn = xyz[nb16 * 3 + 2];
        }
        __syncthreads();

        // ---- phase B: split-K partials; prefetch nei(n+2) ----
        {
            const ulonglong2* w1p = (const ulonglong2*)&W1s[jb][c0];
            const ulonglong2 w1a = w1p[0], w1b = w1p[1], w1c = w1p[2], w1d = w1p[3];
#pragma unroll
            for (int i = 0; i < 8; i++) {
                const int k = i * 2 + khb;
                const ulonglong2* vp = (const ulonglong2*)&wv_s[k][c0];
                ulonglong2 va = vp[0], vb = vp[1], vc = vp[2], vd = vp[3];
                unsigned long long acc = 0ULL;
                ffma2(acc, va.x, w1a.x);
                ffma2(acc, va.y, w1a.y);
                ffma2(acc, vb.x, w1b.x);
                ffma2(acc, vb.y, w1b.y);
                ffma2(acc, vc.x, w1c.x);
                ffma2(acc, vc.y, w1c.y);
                ffma2(acc, vd.x, w1d.x);
                ffma2(acc, vd.y, w1d.y);
                part_s[wrp][k][jb] = lo32(acc) + hi32(acc);
            }
        }
        int nb16_next = 0;
        if (tid < KN && n + 2 * GRIDX < NPTS) nb16_next = nei[(n + 2 * GRIDX) * KN + tid];
        __syncthreads();

        // ---- reduce + relu + logits (shfl), store transposed ----
        {
            const int kk = tid >> 4;
            const int jj = tid & 15;
            float h = g_b1f[jj];
#pragma unroll
            for (int w = 0; w < 8; w++) h += part_s[w][kk][jj];
            h = fmaxf(h, 0.0f);
            float lg = bw2s[jj];
#pragma unroll
            for (int j2 = 0; j2 < CS; j2++)
                lg += __shfl_sync(0xffffffffu, h, j2, 16) * Ww2s[j2][jj];
            lgT_s[jj][kk] = lg;
        }
        __syncthreads();

        // ---- softmax (all 16 half-warps) + t(n+1) from regs ----
        {
            const int j = tid >> 4;
            const int k = tid & 15;
            float v = lgT_s[j][k];
            float m = v;
#pragma unroll
            for (int d = 1; d < 16; d <<= 1)
                m = fmaxf(m, __shfl_xor_sync(0xffffffffu, m, d, 16));
            float e = __expf(v - m);
            float s = e;
#pragma unroll
            for (int d = 1; d < 16; d <<= 1)
                s += __shfl_xor_sync(0xffffffffu, s, d, 16);
            wgt_s[k][j] = e * (1.0f / s);
        }
        if (tid < KN && has_next) {
            float d0 = xnn - xcn, d1 = ynn - ycn, d2 = znn - zcn;
#pragma unroll
            for (int o = 0; o < 3; o++) {
                float v = d0 * g_Wp1f[o] + d1 * g_Wp1f[3 + o] + d2 * g_Wp1f[6 + o] + g_bp1f[o];
                t_s[buf ^ 1][tid][o] = fmaxf(v, 0.0f);
            }
        }
        __syncthreads();

        // ---- phase D-1: in-warp pre-weighted aggregation ----
        {
            const int jq = c4 & 15;
            const float4 wA = *(const float4*)&wgt_s[wrp][jq];
            const float4 wB = *(const float4*)&wgt_s[wrp + 8][jq];
            float4 pa;
            pa.x = wA.x * vp0.x + wB.x * vp1.x;
            pa.y = wA.y * vp0.y + wB.y * vp1.y;
            pa.z = wA.z * vp0.z + wB.z * vp1.z;
            pa.w = wA.w * vp0.w + wB.w * vp1.w;
            *(float4*)&agg_s[wrp][c4] = pa;
        }
        __syncthreads();

        // ---- phase D-2: 8-way cross-warp sum + residual + leaky_relu ----
        if (tid < CH) {
            float acc = 0.0f;
#pragma unroll
            for (int w = 0; w < 8; w++)
                acc += agg_s[w][tid];
            float v = acc + feats[n * CH + tid];
            out[n * CH + tid] = (v > 0.0f) ? v : 0.1f * v;
        }

        if (!has_next) break;
        n = n_next;
        buf ^= 1;
        nb16 = nb16_next;
    }
}

// ---------------- launch ------------------------------------------------------------
extern "C" void kernel_launch(void* const* d_in, const int* in_sizes, int n_in,
                              void* d_out, int out_size) {
    const float* xyz   = (const float*)d_in[0];
    const float* feats = (const float*)d_in[1];
    const int*   nei   = (const int*)d_in[2];
    const float* Wq = (const float*)d_in[3];
    const float* bq = (const float*)d_in[4];
    const float* Wk = (const float*)d_in[5];
    const float* bk = (const float*)d_in[6];
    const float* Wv = (const float*)d_in[7];
    const float* bv = (const float*)d_in[8];
    const float* Wp1 = (const float*)d_in[9];
    const float* bp1 = (const float*)d_in[10];
    const float* p_gamma = (const float*)d_in[11];
    const float* p_beta  = (const float*)d_in[12];
    const float* p_mean  = (const float*)d_in[13];
    const float* p_var   = (const float*)d_in[14];
    const float* Wp2 = (const float*)d_in[15];
    const float* bp2 = (const float*)d_in[16];
    const float* w_gamma = (const float*)d_in[17];
    const float* w_beta  = (const float*)d_in[18];
    const float* w_mean  = (const float*)d_in[19];
    const float* w_var   = (const float*)d_in[20];
    const float* Ww1 = (const float*)d_in[21];
    const float* bw1 = (const float*)d_in[22];
    const float* w1_gamma = (const float*)d_in[23];
    const float* w1_beta  = (const float*)d_in[24];
    const float* w1_mean  = (const float*)d_in[25];
    const float* w1_var   = (const float*)d_in[26];
    const float* Ww2 = (const float*)d_in[27];
    const float* bw2 = (const float*)d_in[28];
    float* out = (float*)d_out;

    prep_kernel<<<1, 256>>>(w_gamma, w_beta, w_mean, w_var, Ww1, bw1, w1_gamma,
                            w1_beta, w1_mean, w1_var, Wp1, bp1, p_gamma, p_beta,
                            p_mean, p_var);
    qkv_gemm<<<1250, 256>>>(feats, Wq, bq, Wk, bk, Wv, bv);
    ncu_align_dummy<<<1, 32>>>();
    pt_main<<<GRIDX, 256>>>(xyz, feats, nei, Wp2, bp2, Ww2, bw2, out);
}